// round 11
// baseline (speedup 1.0000x reference)
#include <cuda_runtime.h>
#include <cstdint>

#define W_POS 5
#define W_NEG 10
#define N_SAMP 15
#define EPS 1e-15f
#define B_MAX 131072
#define REC_CAP (B_MAX * N_SAMP)
#define NBUCKETS 8192
#define BUCKET_SHIFT 7   // key = idx*4+t (< 800000); bucket spans 128 keys = 32 nodes

// Static scratch (no allocations allowed)
__device__ uint2 g_records[REC_CAP];      // 16 MB: (key, b*16+w)
__device__ int   g_histo[NBUCKETS];
__device__ int   g_cursor[NBUCKETS];
__device__ float g_terms[B_MAX * 16];     // 8 MB; slot w=15 never written (stays 0)

__device__ __forceinline__ float4 ldg_evict_last_f4(const void* p, uint64_t policy) {
    float4 r;
    asm volatile("ld.global.nc.L2::cache_hint.v4.f32 {%0,%1,%2,%3}, [%4], %5;"
                 : "=f"(r.x), "=f"(r.y), "=f"(r.z), "=f"(r.w)
                 : "l"(p), "l"(policy));
    return r;
}

__global__ void zero_histo_kernel() {
    int i = blockIdx.x * blockDim.x + threadIdx.x;
    if (i < NBUCKETS) g_histo[i] = 0;
}

__global__ __launch_bounds__(256) void histogram_kernel(
    const int* __restrict__ start_node, const int* __restrict__ pos_samples,
    const int* __restrict__ neg_samples, const int* __restrict__ node_types, int B)
{
    __shared__ int sh[NBUCKETS];
    for (int i = threadIdx.x; i < NBUCKETS; i += blockDim.x) sh[i] = 0;
    __syncthreads();
    for (int b = blockIdx.x * blockDim.x + threadIdx.x; b < B; b += gridDim.x * blockDim.x) {
        const int s = __ldg(start_node + b);
        const int t = __ldg(node_types + s);
#pragma unroll
        for (int w = 0; w < W_POS; w++) {
            int idx = __ldg(pos_samples + b * W_POS + w);
            atomicAdd(&sh[((unsigned)(idx * 4 + t)) >> BUCKET_SHIFT], 1);
        }
#pragma unroll
        for (int w = 0; w < W_NEG; w++) {
            int idx = __ldg(neg_samples + b * W_NEG + w);
            atomicAdd(&sh[((unsigned)(idx * 4 + t)) >> BUCKET_SHIFT], 1);
        }
    }
    __syncthreads();
    for (int i = threadIdx.x; i < NBUCKETS; i += blockDim.x)
        if (sh[i]) atomicAdd(&g_histo[i], sh[i]);
}

__global__ void scan_kernel() {   // 1 block, 1024 threads, 8 bins each
    __shared__ int part[1024];
    const int tid = threadIdx.x;
    int pre[8];
    int acc = 0;
#pragma unroll
    for (int j = 0; j < 8; j++) {
        int v = g_histo[tid * 8 + j];
        pre[j] = acc;
        acc += v;
    }
    part[tid] = acc;
    __syncthreads();
    for (int off = 1; off < 1024; off <<= 1) {
        int v = (tid >= off) ? part[tid - off] : 0;
        __syncthreads();
        part[tid] += v;
        __syncthreads();
    }
    const int base = (tid > 0) ? part[tid - 1] : 0;
#pragma unroll
    for (int j = 0; j < 8; j++)
        g_cursor[tid * 8 + j] = base + pre[j];
}

__global__ __launch_bounds__(256) void scatter_kernel(
    const int* __restrict__ start_node, const int* __restrict__ pos_samples,
    const int* __restrict__ neg_samples, const int* __restrict__ node_types, int B)
{
    for (int b = blockIdx.x * blockDim.x + threadIdx.x; b < B; b += gridDim.x * blockDim.x) {
        const int s = __ldg(start_node + b);
        const int t = __ldg(node_types + s);
#pragma unroll
        for (int w = 0; w < N_SAMP; w++) {
            int idx = (w < W_POS) ? __ldg(pos_samples + b * W_POS + w)
                                  : __ldg(neg_samples + b * W_NEG + (w - W_POS));
            unsigned key = (unsigned)(idx * 4 + t);
            int pos = atomicAdd(&g_cursor[key >> BUCKET_SHIFT], 1);
            g_records[pos] = make_uint2(key, (unsigned)(b * 16 + w));
        }
    }
}

// Warp per record: end-table accesses arrive in sorted (bucketed) order.
__global__ __launch_bounds__(256) void compute_kernel(
    const float* __restrict__ start_embeds, const float* __restrict__ end_embeds,
    const int* __restrict__ start_node, int nrec)
{
    const int r = (blockIdx.x * blockDim.x + threadIdx.x) >> 5;
    if (r >= nrec) return;
    const int lane = threadIdx.x & 31;

    uint64_t policy;  // keep the 102MB start-row hot set resident in L2
    asm volatile("createpolicy.fractional.L2::evict_last.b64 %0, 1.0;" : "=l"(policy));

    const uint2 rec = __ldg(&g_records[r]);
    const unsigned key = rec.x;
    const int b = (int)(rec.y >> 4), w = (int)(rec.y & 15u);
    const int s = __ldg(start_node + b);   // 0.5MB table: L2-resident

    const float4 se = ldg_evict_last_f4(
        (const char*)start_embeds + (uint32_t)s * 512u + (uint32_t)lane * 16u, policy);
    const float4 ee = __ldcs(reinterpret_cast<const float4*>(   // sorted stream: evict-first
        (const char*)end_embeds + key * 512u + (uint32_t)lane * 16u));

    float v = se.x * ee.x + se.y * ee.y + se.z * ee.z + se.w * ee.w;
#pragma unroll
    for (int off = 16; off > 0; off >>= 1)
        v += __shfl_xor_sync(0xffffffffu, v, off);

    if (lane == 0) {
        const float p = 1.0f / (1.0f + expf(-v));
        const float term = (w < W_POS) ? (-1.0f / W_POS) * logf(p + EPS)
                                       : (-1.0f / W_NEG) * logf(1.0f - p + EPS);
        g_terms[rec.y] = term;
    }
}

__global__ __launch_bounds__(256) void finalize_kernel(float* __restrict__ out, int B) {
    const int b = blockIdx.x * blockDim.x + threadIdx.x;
    if (b >= B) return;
    const float4* tp = reinterpret_cast<const float4*>(&g_terms[b * 16]);
    float4 a = tp[0], c = tp[1], d = tp[2], e = tp[3];  // e.w is the never-written slot (=0)
    out[b] = ((a.x + a.y) + (a.z + a.w)) + ((c.x + c.y) + (c.z + c.w))
           + ((d.x + d.y) + (d.z + d.w)) + ((e.x + e.y) + e.z);
}

// ---- Fallback single-pass kernel (known good, R4) for B > B_MAX ----
__global__ __launch_bounds__(256) void mp2vec_fallback(
    const float* __restrict__ start_embeds, const float* __restrict__ end_embeds,
    const int* __restrict__ start_node, const int* __restrict__ pos_samples,
    const int* __restrict__ neg_samples, const int* __restrict__ node_types,
    float* __restrict__ out, int B)
{
    const int warp_id = (blockIdx.x * blockDim.x + threadIdx.x) >> 5;
    if (warp_id >= B) return;
    const int lane = threadIdx.x & 31;
    const int s = __ldg(start_node + warp_id);
    const int t = __ldg(node_types + s);
    const float4 se = __ldg(reinterpret_cast<const float4*>(
        (const char*)start_embeds + (uint32_t)s * 512u + (uint32_t)lane * 16u));
    int idxs[N_SAMP];
#pragma unroll
    for (int w = 0; w < W_POS; w++) idxs[w] = __ldg(pos_samples + warp_id * W_POS + w);
#pragma unroll
    for (int w = 0; w < W_NEG; w++) idxs[W_POS + w] = __ldg(neg_samples + warp_id * W_NEG + w);
    const char* ebase = (const char*)end_embeds + (uint32_t)t * 512u + (uint32_t)lane * 16u;
    float dots[N_SAMP];
#pragma unroll
    for (int w = 0; w < N_SAMP; w++) {
        float4 ee = __ldg(reinterpret_cast<const float4*>(ebase + (uint32_t)idxs[w] * 2048u));
        dots[w] = se.x * ee.x + se.y * ee.y + se.z * ee.z + se.w * ee.w;
    }
#pragma unroll
    for (int off = 16; off > 0; off >>= 1)
#pragma unroll
        for (int w = 0; w < N_SAMP; w++)
            dots[w] += __shfl_xor_sync(0xffffffffu, dots[w], off);
    if (lane == 0) {
        float pa = 0.f, na = 0.f;
#pragma unroll
        for (int w = 0; w < W_POS; w++) pa += logf(1.0f / (1.0f + expf(-dots[w])) + EPS);
#pragma unroll
        for (int w = 0; w < W_NEG; w++) na += logf(1.0f - 1.0f / (1.0f + expf(-dots[W_POS + w])) + EPS);
        out[warp_id] = -pa * (1.0f / W_POS) - na * (1.0f / W_NEG);
    }
}

extern "C" void kernel_launch(void* const* d_in, const int* in_sizes, int n_in,
                              void* d_out, int out_size) {
    const float* start_embeds = (const float*)d_in[0];
    const float* end_embeds   = (const float*)d_in[1];
    const int*   start_node   = (const int*)d_in[2];
    const int*   pos_samples  = (const int*)d_in[3];
    const int*   neg_samples  = (const int*)d_in[4];
    const int*   node_types   = (const int*)d_in[5];
    float*       out          = (float*)d_out;
    const int B = out_size;

    if (B > B_MAX) {  // safety fallback
        mp2vec_fallback<<<(B * 32 + 255) / 256, 256>>>(
            start_embeds, end_embeds, start_node, pos_samples, neg_samples, node_types, out, B);
        return;
    }

    const int nrec = B * N_SAMP;
    zero_histo_kernel<<<(NBUCKETS + 255) / 256, 256>>>();
    histogram_kernel<<<512, 256>>>(start_node, pos_samples, neg_samples, node_types, B);
    scan_kernel<<<1, 1024>>>();
    scatter_kernel<<<512, 256>>>(start_node, pos_samples, neg_samples, node_types, B);
    compute_kernel<<<(nrec + 7) / 8, 256>>>(start_embeds, end_embeds, start_node, nrec);
    finalize_kernel<<<(B + 255) / 256, 256>>>(out, B);
}

// round 13
// speedup vs baseline: 3.7202x; 3.7202x over previous
#include <cuda_runtime.h>
#include <cstdint>

#define W_POS 5
#define W_NEG 10
#define N_SAMP 15
#define EMBED_DIM 128
#define NUM_TYPES 4
#define EPS 1e-15f

__global__ __launch_bounds__(256) void mp2vec_kernel(
    const float* __restrict__ start_embeds,   // [NODE_SIZE, 128]
    const float* __restrict__ end_embeds,     // [NODE_SIZE, 4, 128]
    const int* __restrict__ start_node,       // [B, 1]
    const int* __restrict__ pos_samples,      // [B, 5]
    const int* __restrict__ neg_samples,      // [B, 10]
    const int* __restrict__ node_types,       // [NODE_SIZE]
    float* __restrict__ out,                  // [B]
    int B)
{
    const int warp_id = (blockIdx.x * blockDim.x + threadIdx.x) >> 5;
    if (warp_id >= B) return;
    const int lane = threadIdx.x & 31;

    const int s = __ldg(start_node + warp_id);
    const int t = __ldg(node_types + s);

    // start embedding: lane owns 4 consecutive floats (16B) -> coalesced 512B/warp
    const float4 se = *reinterpret_cast<const float4*>(
        (const char*)start_embeds + (uint32_t)s * 512u + (uint32_t)lane * 16u);

    // Load 15 sample indices (warp-uniform broadcasts; neg rows are 8B-aligned -> int2)
    int idxs[N_SAMP];
#pragma unroll
    for (int w = 0; w < W_POS; w++)
        idxs[w] = __ldg(pos_samples + warp_id * W_POS + w);
    {
        const int2* nrow = reinterpret_cast<const int2*>(neg_samples + warp_id * W_NEG);
#pragma unroll
        for (int j = 0; j < W_NEG / 2; j++) {
            int2 p = __ldg(nrow + j);
            idxs[W_POS + 2 * j]     = p.x;
            idxs[W_POS + 2 * j + 1] = p.y;
        }
    }

    // Gather base: end_embeds + t*512B + lane*16B; per-sample offset fits in u32
    const char* ebase = (const char*)end_embeds + (uint32_t)t * 512u + (uint32_t)lane * 16u;

    float4 es[N_SAMP];
#pragma unroll
    for (int w = 0; w < N_SAMP; w++)
        es[w] = *reinterpret_cast<const float4*>(ebase + (uint32_t)idxs[w] * 2048u);

    // Per-lane partial dots (sample 15 is a dummy zero to make K=16)
    float v[16];
#pragma unroll
    for (int w = 0; w < N_SAMP; w++)
        v[w] = se.x * es[w].x + se.y * es[w].y + se.z * es[w].z + se.w * es[w].w;
    v[15] = 0.0f;

    // Reduce-scatter: 16 shuffles total; lane l ends with sample (l>>1)&15 fully reduced
    float v8[8];
#pragma unroll
    for (int j = 0; j < 8; j++) {
        float send = (lane & 16) ? v[j] : v[j + 8];
        float keep = (lane & 16) ? v[j + 8] : v[j];
        v8[j] = keep + __shfl_xor_sync(0xffffffffu, send, 16);
    }
    float v4[4];
#pragma unroll
    for (int j = 0; j < 4; j++) {
        float send = (lane & 8) ? v8[j] : v8[j + 4];
        float keep = (lane & 8) ? v8[j + 4] : v8[j];
        v4[j] = keep + __shfl_xor_sync(0xffffffffu, send, 8);
    }
    float v2[2];
#pragma unroll
    for (int j = 0; j < 2; j++) {
        float send = (lane & 4) ? v4[j] : v4[j + 2];
        float keep = (lane & 4) ? v4[j + 2] : v4[j];
        v2[j] = keep + __shfl_xor_sync(0xffffffffu, send, 4);
    }
    float s1;
    {
        float send = (lane & 2) ? v2[0] : v2[1];
        float keep = (lane & 2) ? v2[1] : v2[0];
        s1 = keep + __shfl_xor_sync(0xffffffffu, send, 2);
    }
    const float dot = s1 + __shfl_xor_sync(0xffffffffu, s1, 1);

    // Distributed epilogue: lane pair (2l, 2l+1) both hold sample w = lane>>1.
    // Each contributes half the sample's term; dummy sample 15 contributes 0.
    const int w = (lane >> 1) & 15;
    const float p = 1.0f / (1.0f + expf(-dot));
    const float arg = (w < W_POS) ? (p + EPS) : (1.0f - p + EPS);
    // coef = -1/(2*W_POS) or -1/(2*W_NEG) (the 1/2 accounts for pair duplication)
    float coef = (w < W_POS) ? (-0.5f / W_POS) : (-0.5f / W_NEG);
    if (w == 15) coef = 0.0f;
    float term = coef * logf(arg);

    // Final sum of 32 per-lane terms
#pragma unroll
    for (int off = 16; off > 0; off >>= 1)
        term += __shfl_xor_sync(0xffffffffu, term, off);

    if (lane == 0) out[warp_id] = term;
}

extern "C" void kernel_launch(void* const* d_in, const int* in_sizes, int n_in,
                              void* d_out, int out_size) {
    const float* start_embeds = (const float*)d_in[0];
    const float* end_embeds   = (const float*)d_in[1];
    const int*   start_node   = (const int*)d_in[2];
    const int*   pos_samples  = (const int*)d_in[3];
    const int*   neg_samples  = (const int*)d_in[4];
    const int*   node_types   = (const int*)d_in[5];
    float*       out          = (float*)d_out;

    const int B = out_size;
    const int threads = 256;                       // 8 warps/block
    const int warps_per_block = threads / 32;
    const int blocks = (B + warps_per_block - 1) / warps_per_block;
    mp2vec_kernel<<<blocks, threads>>>(start_embeds, end_embeds, start_node,
                                       pos_samples, neg_samples, node_types, out, B);
}